// round 17
// baseline (speedup 1.0000x reference)
#include <cuda_runtime.h>

// ---------------- problem constants ----------------
#define SB    2304          // S = H*W
#define BSR   4608          // B*S
#define DD    64
#define NHH   8
#define FFD   2048
#define NLAYER 8
#define KS    21
#define KK2   441
#define HH    48
#define WWD   48
#define CC    3
#define BB    2
#define EPSV  1e-5f
#define ZSPL  8

typedef unsigned long long u64;

// ---------------- scratch ----------------
__device__ float g_y[BSR * DD];
__device__ float g_y2[BSR * DD];     // ping-pong partner for fused_ln_qkv
__device__ float g_qkv[BSR * 3 * DD];
__device__ float g_attno[BSR * DD];
__device__ float g_part[ZSPL * BSR * DD];
__device__ float g_ff[BSR * FFD];    // used only for final scores

// ---------------- packed f32x2 helpers ----------------
__device__ __forceinline__ u64 fma2(u64 a, u64 b, u64 c) {
    u64 d;
    asm("fma.rn.f32x2 %0, %1, %2, %3;" : "=l"(d) : "l"(a), "l"(b), "l"(c));
    return d;
}
__device__ __forceinline__ u64 mul2(u64 a, u64 b) {
    u64 d;
    asm("mul.rn.f32x2 %0, %1, %2;" : "=l"(d) : "l"(a), "l"(b));
    return d;
}
__device__ __forceinline__ u64 pack2(float lo, float hi) {
    u64 d;
    asm("mov.b64 %0, {%1, %2};" : "=l"(d) : "r"(__float_as_uint(lo)), "r"(__float_as_uint(hi)));
    return d;
}
__device__ __forceinline__ void unpack2(u64 v, float& lo, float& hi) {
    unsigned a, b;
    asm("mov.b64 {%0, %1}, %2;" : "=r"(a), "=r"(b) : "l"(v));
    lo = __uint_as_float(a); hi = __uint_as_float(b);
}
__device__ __forceinline__ float ex2f(float x) {
    float r;
    asm("ex2.approx.f32 %0, %1;" : "=f"(r) : "f"(x));
    return r;
}

// shared inner loop: acc += A(64 rows) x W(64 cols), K=64, FFMA2 4x4 tile
__device__ __forceinline__ void mm64_acc(
    const float (*__restrict__ As)[68], const float (*__restrict__ Ws)[68],
    int tx, int ty, u64 acc[2][4])
{
    #pragma unroll
    for (int k = 0; k < 64; k++) {
        double2 a2 = *(const double2*)&As[k][ty * 4];
        u64 a01 = __double_as_longlong(a2.x);
        u64 a23 = __double_as_longlong(a2.y);
        float4 b4 = *(const float4*)&Ws[k][tx * 4];
        u64 b0 = pack2(b4.x, b4.x);
        u64 b1 = pack2(b4.y, b4.y);
        u64 b2 = pack2(b4.z, b4.z);
        u64 b3 = pack2(b4.w, b4.w);
        acc[0][0] = fma2(a01, b0, acc[0][0]);
        acc[0][1] = fma2(a01, b1, acc[0][1]);
        acc[0][2] = fma2(a01, b2, acc[0][2]);
        acc[0][3] = fma2(a01, b3, acc[0][3]);
        acc[1][0] = fma2(a23, b0, acc[1][0]);
        acc[1][1] = fma2(a23, b1, acc[1][1]);
        acc[1][2] = fma2(a23, b2, acc[1][2]);
        acc[1][3] = fma2(a23, b3, acc[1][3]);
    }
}

// ---------------- conv 3x3 + BN + ReLU -> [B,S,D] ----------------
__global__ __launch_bounds__(256) void conv_bn_relu(
    const float* __restrict__ x, const float* __restrict__ w,
    const float* __restrict__ cb, const float* __restrict__ gma,
    const float* __restrict__ bta, const float* __restrict__ mean,
    const float* __restrict__ var, float* __restrict__ y)
{
    int idx = blockIdx.x * 256 + threadIdx.x;
    if (idx >= BSR * DD) return;
    int d = idx & 63;
    int s = (idx >> 6) % SB;
    int b = idx / (SB * DD);
    int hh = s / WWD, ww = s % WWD;
    float sum = cb[d];
    #pragma unroll
    for (int ci = 0; ci < 3; ci++) {
        #pragma unroll
        for (int kh = 0; kh < 3; kh++) {
            int ih = hh + kh - 1;
            if ((unsigned)ih >= HH) continue;
            #pragma unroll
            for (int kw = 0; kw < 3; kw++) {
                int iw = ww + kw - 1;
                if ((unsigned)iw >= WWD) continue;
                sum += x[((b * CC + ci) * HH + ih) * WWD + iw] *
                       w[((d * CC + ci) * 3 + kh) * 3 + kw];
            }
        }
    }
    sum = (sum - mean[d]) * rsqrtf(var[d] + EPSV) * gma[d] + bta[d];
    y[idx] = fmaxf(sum, 0.0f);
}

// ---------------- gemm64: C[M,N] = A[M,64] @ W[N,64]^T + bias ----------------
template<int RELU>
__global__ __launch_bounds__(256) void gemm64(
    const float* __restrict__ A, const float* __restrict__ W,
    const float* __restrict__ bias, float* __restrict__ C, int N)
{
    __shared__ __align__(16) float As[64][68];
    __shared__ __align__(16) float Ws[64][68];
    int tid = threadIdx.x;
    int rowBase = blockIdx.y * 64;
    int nBase = blockIdx.x * 64;

    int r = tid >> 2, qd = tid & 3;
    {
        const float* ap = A + (rowBase + r) * 64 + qd * 4;
        #pragma unroll
        for (int j = 0; j < 4; j++) {
            float4 v = *(const float4*)(ap + j * 16);
            int k = qd * 4 + j * 16;
            As[k][r] = v.x; As[k + 1][r] = v.y; As[k + 2][r] = v.z; As[k + 3][r] = v.w;
        }
        int n = nBase + r;
        if (n < N) {
            const float* wp = W + n * 64 + qd * 4;
            #pragma unroll
            for (int j = 0; j < 4; j++) {
                float4 v = *(const float4*)(wp + j * 16);
                int k = qd * 4 + j * 16;
                Ws[k][r] = v.x; Ws[k + 1][r] = v.y; Ws[k + 2][r] = v.z; Ws[k + 3][r] = v.w;
            }
        } else {
            #pragma unroll
            for (int j = 0; j < 4; j++) {
                int k = qd * 4 + j * 16;
                Ws[k][r] = 0.f; Ws[k + 1][r] = 0.f; Ws[k + 2][r] = 0.f; Ws[k + 3][r] = 0.f;
            }
        }
    }
    __syncthreads();

    int tx = tid & 15, ty = tid >> 4;
    u64 acc[2][4] = {};
    mm64_acc(As, Ws, tx, ty, acc);

    float rv[4][4];
    #pragma unroll
    for (int v = 0; v < 4; v++) {
        unpack2(acc[0][v], rv[0][v], rv[1][v]);
        unpack2(acc[1][v], rv[2][v], rv[3][v]);
    }
    #pragma unroll
    for (int u = 0; u < 4; u++) {
        int row = rowBase + ty * 4 + u;
        #pragma unroll
        for (int v = 0; v < 4; v++) {
            int n = nBase + tx * 4 + v;
            if (n < N) {
                float val = rv[u][v] + bias[n];
                if (RELU) val = fmaxf(val, 0.0f);
                C[row * N + n] = val;
            }
        }
    }
}

// ---------------- gemm64_ln: Y = LN(Y + A @ W^T + bias), 32-row tiles --------
// grid BSR/32 = 144 blocks (full chip coverage), 256 threads. In-place on Y is
// safe: each block reads/writes only its own 32 rows.
__global__ __launch_bounds__(256) void gemm64_ln(
    const float* __restrict__ A, const float* __restrict__ W,
    const float* __restrict__ bias, float* __restrict__ Y,
    const float* __restrict__ gam, const float* __restrict__ bet)
{
    __shared__ __align__(16) float As[64][68];   // [k][row], rows 0..31 used
    __shared__ __align__(16) float Ws[64][68];   // W, then reused as Z
    int tid = threadIdx.x;
    int rowBase = blockIdx.x * 32;

    // stage A (32 rows x 64), transposed
    {
        int r = tid >> 3, oc = tid & 7;
        const float* ap = A + (rowBase + r) * 64 + oc * 8;
        #pragma unroll
        for (int j = 0; j < 2; j++) {
            float4 v = *(const float4*)(ap + j * 4);
            int k = oc * 8 + j * 4;
            As[k][r] = v.x; As[k + 1][r] = v.y; As[k + 2][r] = v.z; As[k + 3][r] = v.w;
        }
    }
    // stage W (64x64), transposed
    {
        int r = tid >> 2, qd = tid & 3;
        const float* wp = W + r * 64 + qd * 4;
        #pragma unroll
        for (int j = 0; j < 4; j++) {
            float4 v = *(const float4*)(wp + j * 16);
            int k = qd * 4 + j * 16;
            Ws[k][r] = v.x; Ws[k + 1][r] = v.y; Ws[k + 2][r] = v.z; Ws[k + 3][r] = v.w;
        }
    }
    __syncthreads();

    int tx = tid & 15, ty = tid >> 4;   // tx: 4 cols, ty: 2 rows
    u64 acc[4] = {};
    #pragma unroll
    for (int k = 0; k < 64; k++) {
        u64 a01 = *(const u64*)&As[k][ty * 2];
        float4 b4 = *(const float4*)&Ws[k][tx * 4];
        u64 b0 = pack2(b4.x, b4.x);
        u64 b1 = pack2(b4.y, b4.y);
        u64 b2 = pack2(b4.z, b4.z);
        u64 b3 = pack2(b4.w, b4.w);
        acc[0] = fma2(a01, b0, acc[0]);
        acc[1] = fma2(a01, b1, acc[1]);
        acc[2] = fma2(a01, b2, acc[2]);
        acc[3] = fma2(a01, b3, acc[3]);
    }
    float rv[2][4];
    #pragma unroll
    for (int v = 0; v < 4; v++) unpack2(acc[v], rv[0][v], rv[1][v]);
    __syncthreads();   // done reading As/Ws; reuse Ws as Z

    {
        int c0 = tx * 4;
        float4 bb = *(const float4*)(bias + c0);
        float bv[4] = {bb.x, bb.y, bb.z, bb.w};
        #pragma unroll
        for (int u = 0; u < 2; u++) {
            int row = ty * 2 + u;
            float4 yv = *(const float4*)&Y[(rowBase + row) * 64 + c0];
            Ws[row][c0 + 0] = rv[u][0] + bv[0] + yv.x;
            Ws[row][c0 + 1] = rv[u][1] + bv[1] + yv.y;
            Ws[row][c0 + 2] = rv[u][2] + bv[2] + yv.z;
            Ws[row][c0 + 3] = rv[u][3] + bv[3] + yv.w;
        }
    }
    __syncthreads();

    int wid = tid >> 5, lane = tid & 31;
    #pragma unroll 1
    for (int i = 0; i < 4; i++) {
        int row = wid * 4 + i;
        float z0 = Ws[row][lane];
        float z1 = Ws[row][lane + 32];
        float s = z0 + z1;
        float ss = z0 * z0 + z1 * z1;
        #pragma unroll
        for (int off = 16; off; off >>= 1) {
            s  += __shfl_xor_sync(0xFFFFFFFFu, s, off);
            ss += __shfl_xor_sync(0xFFFFFFFFu, ss, off);
        }
        float mean = s * (1.0f / 64.0f);
        float var = ss * (1.0f / 64.0f) - mean * mean;
        float inv = rsqrtf(var + EPSV);
        Y[(rowBase + row) * 64 + lane]      = (z0 - mean) * inv * gam[lane]      + bet[lane];
        Y[(rowBase + row) * 64 + 32 + lane] = (z1 - mean) * inv * gam[32 + lane] + bet[32 + lane];
    }
}

// ============================================================================
// fused_ln_qkv: Ynew = LN(Yin + sum(part) + b2) -> Yout;
//               qkv_chunk = Ynew @ Win_c^T + b
// grid (3, BSR/64) = 216 blocks, 256 threads. Yin is READ-ONLY (no race);
// nc==0 blocks write Ynew to Yout (separate buffer, ping-pong).
// ============================================================================
__global__ __launch_bounds__(256) void fused_ln_qkv(
    const float* __restrict__ Yin, float* __restrict__ Yout,
    const float* __restrict__ part, const float* __restrict__ b2,
    const float* __restrict__ gam, const float* __restrict__ bet,
    const float* __restrict__ Win, const float* __restrict__ binq,
    float* __restrict__ qkv)
{
    __shared__ __align__(16) float As[64][68];   // LN output, transposed [k][row]
    __shared__ __align__(16) float Ws[64][68];
    int tid = threadIdx.x;
    int nc = blockIdx.x;
    int rowBase = blockIdx.y * 64;
    int nBase = nc * 64;
    int wid = tid >> 5, lane = tid & 31;

    // merge + residual + LN, store transposed into As; nc==0 writes Yout
    #pragma unroll 1
    for (int i = 0; i < 8; i++) {
        int row = wid * 8 + i;
        int grow = rowBase + row;
        float z0 = Yin[grow * 64 + lane]      + b2[lane];
        float z1 = Yin[grow * 64 + 32 + lane] + b2[32 + lane];
        #pragma unroll
        for (int z = 0; z < ZSPL; z++) {
            z0 += part[z * (BSR * 64) + grow * 64 + lane];
            z1 += part[z * (BSR * 64) + grow * 64 + 32 + lane];
        }
        float s = z0 + z1;
        float ss = z0 * z0 + z1 * z1;
        #pragma unroll
        for (int off = 16; off; off >>= 1) {
            s  += __shfl_xor_sync(0xFFFFFFFFu, s, off);
            ss += __shfl_xor_sync(0xFFFFFFFFu, ss, off);
        }
        float mean = s * (1.0f / 64.0f);
        float var = ss * (1.0f / 64.0f) - mean * mean;
        float inv = rsqrtf(var + EPSV);
        float n0 = (z0 - mean) * inv * gam[lane]      + bet[lane];
        float n1 = (z1 - mean) * inv * gam[32 + lane] + bet[32 + lane];
        As[lane][row]      = n0;
        As[lane + 32][row] = n1;
        if (nc == 0) {
            Yout[grow * 64 + lane]      = n0;
            Yout[grow * 64 + 32 + lane] = n1;
        }
    }
    // stage W chunk (rows nBase..nBase+63 of Win[192][64]), transposed
    {
        int r = tid >> 2, qd = tid & 3;
        const float* wp = Win + (nBase + r) * 64 + qd * 4;
        #pragma unroll
        for (int j = 0; j < 4; j++) {
            float4 v = *(const float4*)(wp + j * 16);
            int k = qd * 4 + j * 16;
            Ws[k][r] = v.x; Ws[k + 1][r] = v.y; Ws[k + 2][r] = v.z; Ws[k + 3][r] = v.w;
        }
    }
    __syncthreads();

    int tx = tid & 15, ty = tid >> 4;
    u64 acc[2][4] = {};
    mm64_acc(As, Ws, tx, ty, acc);

    float rv[4][4];
    #pragma unroll
    for (int v = 0; v < 4; v++) {
        unpack2(acc[0][v], rv[0][v], rv[1][v]);
        unpack2(acc[1][v], rv[2][v], rv[3][v]);
    }
    float4 bb = *(const float4*)(binq + nBase + tx * 4);
    float bv[4] = {bb.x, bb.y, bb.z, bb.w};
    #pragma unroll
    for (int u = 0; u < 4; u++) {
        int row = rowBase + ty * 4 + u;
        #pragma unroll
        for (int v = 0; v < 4; v++)
            qkv[row * 192 + nBase + tx * 4 + v] = rv[u][v] + bv[v];
    }
}

// ============================================================================
// ffn_fused: partial[z] = relu(Y @ W1_z^T + b1_z) @ W2_z^T  (R14, unchanged)
// ============================================================================
__global__ __launch_bounds__(256, 4) void ffn_fused(
    const float* __restrict__ Y, const float* __restrict__ W1,
    const float* __restrict__ b1, const float* __restrict__ W2,
    float* __restrict__ Cpart)
{
    extern __shared__ __align__(16) float smraw[];
    float (*Ys)[68]  = (float(*)[68])smraw;
    float (*Wst)[68] = (float(*)[68])(smraw + 64 * 68);
    float (*F1)[68]  = (float(*)[68])(smraw + 2 * 64 * 68);

    int tid = threadIdx.x;
    int rowBase = blockIdx.x * 64;
    int z = blockIdx.y;
    int r = tid >> 2, qd = tid & 3;
    int tx = tid & 15, ty = tid >> 4;

    {
        const float* yp = Y + (rowBase + r) * 64 + qd * 4;
        #pragma unroll
        for (int j = 0; j < 4; j++) {
            float4 v = *(const float4*)(yp + j * 16);
            int k = qd * 4 + j * 16;
            Ys[k][r] = v.x; Ys[k + 1][r] = v.y; Ys[k + 2][r] = v.z; Ys[k + 3][r] = v.w;
        }
    }

    u64 acc2[2][4] = {};

    #pragma unroll 1
    for (int c = 0; c < FFD / (ZSPL * 64); c++) {
        int kcol = z * (FFD / ZSPL) + c * 64;
        __syncthreads();
        {
            const float* wp = W1 + (kcol + r) * 64 + qd * 4;
            #pragma unroll
            for (int j = 0; j < 4; j++) {
                float4 v = *(const float4*)(wp + j * 16);
                int k = qd * 4 + j * 16;
                Wst[k][r] = v.x; Wst[k + 1][r] = v.y; Wst[k + 2][r] = v.z; Wst[k + 3][r] = v.w;
            }
        }
        __syncthreads();

        u64 a1[2][4] = {};
        mm64_acc((const float(*)[68])Ys, (const float(*)[68])Wst, tx, ty, a1);
        float rv[4][4];
        #pragma unroll
        for (int v = 0; v < 4; v++) {
            unpack2(a1[0][v], rv[0][v], rv[1][v]);
            unpack2(a1[1][v], rv[2][v], rv[3][v]);
        }
        __syncthreads();

        {
            float4 bb = *(const float4*)(b1 + kcol + tx * 4);
            float bv[4] = {bb.x, bb.y, bb.z, bb.w};
            #pragma unroll
            for (int u = 0; u < 4; u++) {
                int row = ty * 4 + u;
                #pragma unroll
                for (int v = 0; v < 4; v++)
                    F1[tx * 4 + v][row] = fmaxf(rv[u][v] + bv[v], 0.0f);
            }
            const float* wp = W2 + r * FFD + kcol + qd * 4;
            #pragma unroll
            for (int j = 0; j < 4; j++) {
                float4 v = *(const float4*)(wp + j * 16);
                int k = qd * 4 + j * 16;
                Wst[k][r] = v.x; Wst[k + 1][r] = v.y; Wst[k + 2][r] = v.z; Wst[k + 3][r] = v.w;
            }
        }
        __syncthreads();

        mm64_acc((const float(*)[68])F1, (const float(*)[68])Wst, tx, ty, acc2);
    }

    float* Cp = Cpart + z * (BSR * 64);
    float rv2[4][4];
    #pragma unroll
    for (int v = 0; v < 4; v++) {
        unpack2(acc2[0][v], rv2[0][v], rv2[1][v]);
        unpack2(acc2[1][v], rv2[2][v], rv2[3][v]);
    }
    #pragma unroll
    for (int u = 0; u < 4; u++) {
        int row = rowBase + ty * 4 + u;
        *(float4*)&Cp[row * 64 + tx * 4] =
            make_float4(rv2[u][0], rv2[u][1], rv2[u][2], rv2[u][3]);
    }
}

// ---------------- merge split-K partials + bias + residual + LN (layer 7) -----
__global__ __launch_bounds__(256) void add_ln_ff(
    float* __restrict__ Y, const float* __restrict__ part,
    const float* __restrict__ bias,
    const float* __restrict__ gam, const float* __restrict__ bet)
{
    int row = blockIdx.x * 8 + (threadIdx.x >> 5);
    int lane = threadIdx.x & 31;
    float z0 = Y[row * 64 + lane]      + bias[lane];
    float z1 = Y[row * 64 + 32 + lane] + bias[32 + lane];
    #pragma unroll
    for (int z = 0; z < ZSPL; z++) {
        z0 += part[z * (BSR * 64) + row * 64 + lane];
        z1 += part[z * (BSR * 64) + row * 64 + 32 + lane];
    }
    float s = z0 + z1;
    float ss = z0 * z0 + z1 * z1;
    #pragma unroll
    for (int off = 16; off; off >>= 1) {
        s  += __shfl_xor_sync(0xFFFFFFFFu, s, off);
        ss += __shfl_xor_sync(0xFFFFFFFFu, ss, off);
    }
    float mean = s * (1.0f / 64.0f);
    float var = ss * (1.0f / 64.0f) - mean * mean;
    float inv = rsqrtf(var + EPSV);
    Y[row * 64 + lane]      = (z0 - mean) * inv * gam[lane]      + bet[lane];
    Y[row * 64 + 32 + lane] = (z1 - mean) * inv * gam[32 + lane] + bet[32 + lane];
}

// ---------------- attention: unshifted softmax (unchanged) --------------------
__global__ __launch_bounds__(384) void attention_kernel(
    const float* __restrict__ qkv, float* __restrict__ o)
{
    __shared__ __align__(16) float Kt[3][128][8];
    __shared__ __align__(16) float Vt[3][128][8];
    __shared__ float Ss[2][128];
    __shared__ float Accs[2][128][8];

    int tid = threadIdx.x;
    int g = tid >> 7;          // 0..2
    int t = tid & 127;
    int bh = blockIdx.x;
    int b = bh >> 3, h = bh & 7;
    int qbase = blockIdx.y * 128;
    int srow = b * SB + qbase + t;

    const float QS = 0.35355339059327373f * 1.4426950408889634f;
    const float* qp = qkv + srow * 192 + h * 8;
    float4 qa = *(const float4*)qp;
    float4 qb = *(const float4*)(qp + 4);
    u64 q01 = pack2(qa.x * QS, qa.y * QS);
    u64 q23 = pack2(qa.z * QS, qa.w * QS);
    u64 q45 = pack2(qb.x * QS, qb.y * QS);
    u64 q67 = pack2(qb.z * QS, qb.w * QS);

    float sum = 0.0f;
    u64 a01 = 0, a23 = 0, a45 = 0, a67 = 0;

    for (int tile = g; tile < 18; tile += 3) {
        int krow = b * SB + tile * 128 + t;
        const float* kp = qkv + krow * 192 + 64 + h * 8;
        float4 k0 = *(const float4*)kp;
        float4 k1 = *(const float4*)(kp + 4);
        float4 v0 = *(const float4*)(kp + 64);
        float4 v1 = *(const float4*)(kp + 68);
        *(float4*)&Kt[g][t][0] = k0; *(float4*)&Kt[g][t][4] = k1;
        *(float4*)&Vt[g][t][0] = v0; *(float4*)&Vt[g][t][4] = v1;
        asm volatile("bar.sync %0, 128;" :: "r"(g + 1) : "memory");

        #pragma unroll 4
        for (int kk = 0; kk < 128; kk++) {
            double2 ka = *(const double2*)&Kt[g][kk][0];
            double2 kb2 = *(const double2*)&Kt[g][kk][4];
            u64 d = mul2(q01, __double_as_longlong(ka.x));
            d = fma2(q23, __double_as_longlong(ka.y), d);
            d = fma2(q45, __double_as_longlong(kb2.x), d);
            d = fma2(q67, __double_as_longlong(kb2.y), d);
            float lo, hi;
            unpack2(d, lo, hi);
            float e = ex2f(lo + hi);
            sum += e;
            u64 pe = pack2(e, e);
            double2 va = *(const double2*)&Vt[g][kk][0];
            double2 vb2 = *(const double2*)&Vt[g][kk][4];
            a01 = fma2(pe, __double_as_longlong(va.x), a01);
            a23 = fma2(pe, __double_as_longlong(va.y), a23);
            a45 = fma2(pe, __double_as_longlong(vb2.x), a45);
            a67 = fma2(pe, __double_as_longlong(vb2.y), a67);
        }
        asm volatile("bar.sync %0, 128;" :: "r"(g + 1) : "memory");
    }

    float av[8];
    unpack2(a01, av[0], av[1]);
    unpack2(a23, av[2], av[3]);
    unpack2(a45, av[4], av[5]);
    unpack2(a67, av[6], av[7]);

    if (g > 0) {
        Ss[g - 1][t] = sum;
        #pragma unroll
        for (int j = 0; j < 8; j++) Accs[g - 1][t][j] = av[j];
    }
    __syncthreads();
    if (g == 0) {
        sum += Ss[0][t] + Ss[1][t];
        #pragma unroll
        for (int j = 0; j < 8; j++)
            av[j] += Accs[0][t][j] + Accs[1][t][j];
        float inv = 1.0f / sum;
        float* op = o + srow * 64 + h * 8;
        float4 o0 = make_float4(av[0]*inv, av[1]*inv, av[2]*inv, av[3]*inv);
        float4 o1 = make_float4(av[4]*inv, av[5]*inv, av[6]*inv, av[7]*inv);
        *(float4*)op = o0;
        *(float4*)(op + 4) = o1;
    }
}

// ---------------- final softmax over 441 + transpose to [B,441,S] ----------
__global__ __launch_bounds__(128) void softmax_t_kernel(
    const float* __restrict__ sc, float* __restrict__ outK)
{
    __shared__ float red[128];
    int row = blockIdx.x;
    int b = row / SB, s = row % SB;
    int tid = threadIdx.x;
    float v[4];
    float mx = -1e30f;
    #pragma unroll
    for (int i = 0; i < 4; i++) {
        int p = tid + i * 128;
        v[i] = (p < KK2) ? sc[row * KK2 + p] : -1e30f;
        mx = fmaxf(mx, v[i]);
    }
    red[tid] = mx; __syncthreads();
    for (int o = 64; o; o >>= 1) { if (tid < o) red[tid] = fmaxf(red[tid], red[tid + o]); __syncthreads(); }
    float m = red[0]; __syncthreads();
    float sum = 0.0f;
    #pragma unroll
    for (int i = 0; i < 4; i++) {
        int p = tid + i * 128;
        v[i] = (p < KK2) ? __expf(v[i] - m) : 0.0f;
        sum += v[i];
    }
    red[tid] = sum; __syncthreads();
    for (int o = 64; o; o >>= 1) { if (tid < o) red[tid] += red[tid + o]; __syncthreads(); }
    float inv = 1.0f / red[0];
    #pragma unroll
    for (int i = 0; i < 4; i++) {
        int p = tid + i * 128;
        if (p < KK2) outK[(b * KK2 + p) * SB + s] = v[i] * inv;
    }
}

// ---------------- apply predicted kernel (reflect pad), 128-thr blocks --------
__global__ __launch_bounds__(128) void apply_kernel(
    const float* __restrict__ x, const float* __restrict__ kern, float* __restrict__ out)
{
    int idx = blockIdx.x * 128 + threadIdx.x;
    if (idx >= BB * CC * HH * WWD) return;
    int ww = idx % WWD;
    int hh = (idx / WWD) % HH;
    int c = (idx / (HH * WWD)) % CC;
    int b = idx / (CC * HH * WWD);
    const float* kb = kern + b * KK2 * SB + hh * WWD + ww;
    const float* xb = x + (b * CC + c) * HH * WWD;
    float acc = 0.0f;
    #pragma unroll 1
    for (int kh = 0; kh < KS; kh++) {
        int ih = hh + kh - 10;
        if (ih < 0) ih = -ih;
        else if (ih >= HH) ih = 2 * HH - 2 - ih;
        const float* xr = xb + ih * WWD;
        #pragma unroll
        for (int kw = 0; kw < KS; kw++) {
            int iw = ww + kw - 10;
            if (iw < 0) iw = -iw;
            else if (iw >= WWD) iw = 2 * WWD - 2 - iw;
            acc = fmaf(xr[iw], kb[(kh * KS + kw) * SB], acc);
        }
    }
    out[idx] = acc;
}

// ---------------- host launcher ----------------
extern "C" void kernel_launch(void* const* d_in, const int* in_sizes, int n_in,
                              void* d_out, int out_size)
{
    const float* x        = (const float*)d_in[0];
    const float* conv1_w  = (const float*)d_in[1];
    const float* conv1_b  = (const float*)d_in[2];
    const float* bn_gamma = (const float*)d_in[3];
    const float* bn_beta  = (const float*)d_in[4];
    const float* bn_mean  = (const float*)d_in[5];
    const float* bn_var   = (const float*)d_in[6];
    const float* attn_in_w  = (const float*)d_in[7];
    const float* attn_in_b  = (const float*)d_in[8];
    const float* attn_out_w = (const float*)d_in[9];
    const float* attn_out_b = (const float*)d_in[10];
    const float* lin1_w   = (const float*)d_in[11];
    const float* lin1_b   = (const float*)d_in[12];
    const float* lin2_w   = (const float*)d_in[13];
    const float* lin2_b   = (const float*)d_in[14];
    const float* ln1_g    = (const float*)d_in[15];
    const float* ln1_b    = (const float*)d_in[16];
    const float* ln2_g    = (const float*)d_in[17];
    const float* ln2_b    = (const float*)d_in[18];
    const float* last_w   = (const float*)d_in[19];
    const float* last_b   = (const float*)d_in[20];

    float* out = (float*)d_out;
    float* kern = out + BB * CC * HH * WWD;

    float *pyA, *pyB, *pqkv, *pattno, *ppart, *pff;
    cudaGetSymbolAddress((void**)&pyA, g_y);
    cudaGetSymbolAddress((void**)&pyB, g_y2);
    cudaGetSymbolAddress((void**)&pqkv, g_qkv);
    cudaGetSymbolAddress((void**)&pattno, g_attno);
    cudaGetSymbolAddress((void**)&ppart, g_part);
    cudaGetSymbolAddress((void**)&pff, g_ff);

    const int FFN_SMEM = 3 * 64 * 68 * sizeof(float);   // 52224 B
    cudaFuncSetAttribute(ffn_fused, cudaFuncAttributeMaxDynamicSharedMemorySize, FFN_SMEM);

    conv_bn_relu<<<(BSR * DD + 255) / 256, 256>>>(x, conv1_w, conv1_b, bn_gamma,
                                                  bn_beta, bn_mean, bn_var, pyA);

    // layer-0 qkv from conv output
    gemm64<0><<<dim3(3, BSR / 64), 256>>>(
        pyA, attn_in_w, attn_in_b, pqkv, 192);

    float* ycur = pyA;
    float* ynext = pyB;
    for (int l = 0; l < NLAYER; l++) {
        // attention -> attno [4608,64]
        attention_kernel<<<dim3(BB * NHH, SB / 128), 384>>>(pqkv, pattno);
        // y = LN(y + attno @ Wout^T + b)   (fused, 32-row tiles, in-place)
        gemm64_ln<<<BSR / 32, 256>>>(
            pattno, attn_out_w + l * DD * DD, attn_out_b + l * DD, ycur,
            ln1_g + l * DD, ln1_b + l * DD);
        // FFN: partial[z] = relu(y @ W1_z^T + b1_z) @ W2_z^T
        ffn_fused<<<dim3(BSR / 64, ZSPL), 256, FFN_SMEM>>>(
            ycur, lin1_w + l * FFD * DD, lin1_b + l * FFD,
            lin2_w + l * DD * FFD, ppart);
        if (l < NLAYER - 1) {
            // ynext = LN(ycur + sum(partials) + b2); qkv(l+1) = ynext @ Win^T + b
            fused_ln_qkv<<<dim3(3, BSR / 64), 256>>>(
                ycur, ynext, ppart, lin2_b + l * DD,
                ln2_g + l * DD, ln2_b + l * DD,
                attn_in_w + (l + 1) * 192 * DD, attn_in_b + (l + 1) * 192, pqkv);
            float* tmp = ycur; ycur = ynext; ynext = tmp;
        } else {
            add_ln_ff<<<BSR / 8, 256>>>(ycur, ppart, lin2_b + l * DD,
                                        ln2_g + l * DD, ln2_b + l * DD);
        }
    }

    // scores = y @ last_w^T + last_b  [4608,441]
    gemm64<0><<<dim3((KK2 + 63) / 64, BSR / 64), 256>>>(ycur, last_w, last_b, pff, KK2);
    softmax_t_kernel<<<BSR, 128>>>(pff, kern);
    apply_kernel<<<(BB * CC * HH * WWD + 127) / 128, 128>>>(x, kern, out);
}